// round 8
// baseline (speedup 1.0000x reference)
#include <cuda_runtime.h>
#include <cuda_fp16.h>
#include <math.h>
#include <stdint.h>

#define BATCH 4
#define NPIX  4096
#define CHIGH 256
#define CLOW  128
#define HEADS 4
#define HDIM  32
#define FFN   256

// ======================= helpers =======================
__device__ __forceinline__ uint32_t smem_u32(const void* p) {
    uint32_t a;
    asm("{ .reg .u64 t; cvta.to.shared.u64 t, %1; cvt.u32.u64 %0, t; }" : "=r"(a) : "l"(p));
    return a;
}

#define LDSM_X4(r0, r1, r2, r3, addr) \
    asm volatile("ldmatrix.sync.aligned.m8n8.x4.shared.b16 {%0,%1,%2,%3}, [%4];" \
        : "=r"(r0), "=r"(r1), "=r"(r2), "=r"(r3) : "r"(addr))
#define LDSM_X2(r0, r1, addr) \
    asm volatile("ldmatrix.sync.aligned.m8n8.x2.shared.b16 {%0,%1}, [%2];" \
        : "=r"(r0), "=r"(r1) : "r"(addr))
#define LDSM_X4_T(r0, r1, r2, r3, addr) \
    asm volatile("ldmatrix.sync.aligned.m8n8.x4.trans.shared.b16 {%0,%1,%2,%3}, [%4];" \
        : "=r"(r0), "=r"(r1), "=r"(r2), "=r"(r3) : "r"(addr))
#define LDSM_X2_T(r0, r1, addr) \
    asm volatile("ldmatrix.sync.aligned.m8n8.x2.trans.shared.b16 {%0,%1}, [%2];" \
        : "=r"(r0), "=r"(r1) : "r"(addr))
#define MMA16816(c, a, b) \
    asm volatile("mma.sync.aligned.m16n8k16.row.col.f32.f16.f16.f32 " \
        "{%0,%1,%2,%3}, {%4,%5,%6,%7}, {%8,%9}, {%0,%1,%2,%3};" \
        : "+f"((c)[0]), "+f"((c)[1]), "+f"((c)[2]), "+f"((c)[3]) \
        : "r"((a)[0]), "r"((a)[1]), "r"((a)[2]), "r"((a)[3]), "r"((b)[0]), "r"((b)[1]))
#define EX2_F16X2(out, in) \
    asm("ex2.approx.f16x2 %0, %1;" : "=r"(out) : "r"(in))

__device__ __forceinline__ void cpa16(uint32_t dst, const void* src) {
    asm volatile("cp.async.ca.shared.global [%0], [%1], 16;" :: "r"(dst), "l"(src));
}
#define CP_COMMIT() asm volatile("cp.async.commit_group;" ::: "memory")
#define CP_WAIT0()  asm volatile("cp.async.wait_group 0;" ::: "memory")
#define CP_WAIT1()  asm volatile("cp.async.wait_group 1;" ::: "memory")

__device__ __forceinline__ uint32_t pack_hf2(float a, float b) {
    __half2 h = __floats2half2_rn(a, b);
    return *(uint32_t*)&h;
}

// ======================= scratch =======================
__device__ __half g_hh [BATCH*CHIGH*NPIX];   // high raw fp16
__device__ __half g_lh [BATCH*CLOW *NPIX];   // low raw fp16
__device__ __half g_q  [BATCH*CLOW *NPIX];   // [b][c][n]
__device__ __half g_k  [BATCH*CLOW *NPIX];
__device__ __half g_v  [BATCH*CLOW *NPIX];
__device__ __half g_ao [BATCH*CLOW *NPIX];
__device__ float  g_x  [BATCH*CLOW *NPIX];
__device__ __half g_xh [BATCH*CLOW *NPIX];   // x raw fp16 (for ffn1)
__device__ __half g_mid[BATCH*FFN  *NPIX];
__device__ float g_part[3][BATCH][64][2];
__device__ float g_mu[3][BATCH];
__device__ float g_rs[3][BATCH];
// folded fp16 weights (per-batch where groupnorm folds in) + per-channel biases
__device__ __half g_whq[BATCH*CLOW*CHIGH];
__device__ __half g_whk[BATCH*CLOW*CLOW];
__device__ __half g_whv[BATCH*CLOW*CLOW];
__device__ __half g_wh1[BATCH*FFN*CLOW];
__device__ __half g_whp[CLOW*CLOW];
__device__ __half g_wh2[CLOW*FFN];
__device__ float g_bias[4][BATCH][256];      // 0=q,1=k,2=v,3=ffn1

// ================= input convert fp32 -> fp16 =================
__global__ void convert_inputs(const float* __restrict__ high, const float* __restrict__ low) {
    int z = blockIdx.y;
    const float* src = z ? low : high;
    __half* dst = z ? g_lh : g_hh;
    int n = z ? BATCH*CLOW*NPIX : BATCH*CHIGH*NPIX;
    int i = (blockIdx.x * 256 + threadIdx.x) * 4;
    if (i < n) {
        float4 v = *(const float4*)(src + i);
        uint2 p; p.x = pack_hf2(v.x, v.y); p.y = pack_hf2(v.z, v.w);
        *(uint2*)(dst + i) = p;
    }
}

// ================= GroupNorm stats (deterministic 2-stage) =================
__global__ void stats_partial2(const float* __restrict__ high, const float* __restrict__ low) {
    int b = blockIdx.x, ch = blockIdx.y, z = blockIdx.z;
    int perSample = z ? CLOW*NPIX : CHIGH*NPIX;
    int perChunk  = perSample / 32;
    const float* p = (z ? low : high) + (size_t)b*perSample + (size_t)ch*perChunk;
    float s = 0.f, ss = 0.f;
    for (int i = threadIdx.x*4; i < perChunk; i += blockDim.x*4) {
        float4 v = *(const float4*)(p + i);
        s  += v.x + v.y + v.z + v.w;
        ss += v.x*v.x + v.y*v.y + v.z*v.z + v.w*v.w;
    }
    #pragma unroll
    for (int o = 16; o; o >>= 1) {
        s  += __shfl_xor_sync(0xffffffffu, s,  o);
        ss += __shfl_xor_sync(0xffffffffu, ss, o);
    }
    __shared__ float sh[2][8];
    int w = threadIdx.x >> 5;
    if ((threadIdx.x & 31) == 0) { sh[0][w] = s; sh[1][w] = ss; }
    __syncthreads();
    if (threadIdx.x == 0) {
        float S = 0.f, SS = 0.f;
        #pragma unroll
        for (int i = 0; i < 8; i++) { S += sh[0][i]; SS += sh[1][i]; }
        g_part[z][b][ch][0] = S; g_part[z][b][ch][1] = SS;
    }
}

__global__ void stats_final(int base, float cnt0, float cnt1, int nch) {
    int b = blockIdx.x, idx = base + blockIdx.y, t = threadIdx.x;
    float cnt = blockIdx.y ? cnt1 : cnt0;
    float s = g_part[idx][b][t][0], ss = g_part[idx][b][t][1];
    if (nch > 32) { s += g_part[idx][b][t+32][0]; ss += g_part[idx][b][t+32][1]; }
    #pragma unroll
    for (int o = 16; o; o >>= 1) {
        s  += __shfl_xor_sync(0xffffffffu, s,  o);
        ss += __shfl_xor_sync(0xffffffffu, ss, o);
    }
    if (t == 0) {
        float mu = s / cnt;
        float var = ss / cnt - mu * mu;
        g_mu[idx][b] = mu;
        g_rs[idx][b] = rsqrtf(var + 1e-5f);
    }
}

// ================= weight folds =================
// groupnorm fold: out = W @ (x*s + t) = (W*diag(s)) @ x + (W@t)
__global__ void fold_qkvp(const float* __restrict__ Wq, const float* __restrict__ Wk,
                          const float* __restrict__ Wv, const float* __restrict__ Wp,
                          const float* __restrict__ W2,
                          const float* __restrict__ nhw, const float* __restrict__ nhb,
                          const float* __restrict__ nlw, const float* __restrict__ nlb,
                          float qscale) {
    int b = blockIdx.x, which = blockIdx.y, o = threadIdx.x;  // 128 threads
    if (which <= 2) {
        int K = (which == 0) ? CHIGH : CLOW;
        int sidx = (which == 0) ? 0 : 1;
        const float* nw  = (which == 0) ? nhw : nlw;
        const float* nbv = (which == 0) ? nhb : nlb;
        const float* src = (which == 0) ? Wq : ((which == 1) ? Wk : Wv);
        __half* dstb = ((which == 0) ? g_whq : ((which == 1) ? g_whk : g_whv))
                       + (size_t)b*CLOW*K;
        float alpha = (which == 0) ? qscale : 1.0f;
        float mu = g_mu[sidx][b], rs = g_rs[sidx][b];
        const float* s = src + (size_t)o*K;
        __half* d = dstb + (size_t)o*K;
        float bias = 0.f;
        for (int c = 0; c < K; c++) {
            float w = s[c];
            float sc = nw[c]*rs;
            d[c] = __float2half(w*sc*alpha);
            bias += w*(nbv[c] - mu*sc);
        }
        g_bias[which][b][o] = bias*alpha;
    } else if (b == 0) {
        const float* src = (which == 3) ? Wp : W2;
        __half* dst = (which == 3) ? g_whp : g_wh2;
        int n = (which == 3) ? CLOW*CLOW : CLOW*FFN;
        for (int i = o*4; i < n; i += 512) {
            float4 v = *(const float4*)(src + i);
            uint2 p; p.x = pack_hf2(v.x, v.y); p.y = pack_hf2(v.z, v.w);
            *(uint2*)(dst + i) = p;
        }
    }
}

__global__ void fold_ffn1(const float* __restrict__ W1, const float* __restrict__ nfw,
                          const float* __restrict__ nfb) {
    int b = blockIdx.x, o = threadIdx.x;  // 256 threads
    float mu = g_mu[2][b], rs = g_rs[2][b];
    const float* s = W1 + (size_t)o*CLOW;
    __half* d = g_wh1 + (size_t)b*FFN*CLOW + (size_t)o*CLOW;
    float bias = 0.f;
    for (int c = 0; c < CLOW; c++) {
        float w = s[c];
        float sc = nfw[c]*rs;
        d[c] = __float2half(w*sc);
        bias += w*(nfb[c] - mu*sc);
    }
    g_bias[3][b][o] = bias;
}

// ================= dual-warpgroup TC GEMM, all-fp16, cp.async =================
// EP: 1 = f16 out; 2 = fp32 out = res + gamma*(acc) (+stats, +dual fp16 x); 3 = gelu->f16
template<int EP, int GTILES, int PERBATCH, int HASBIAS, int DOSTATS, int DUALX>
__global__ void __launch_bounds__(256, 2)
gemm2(const __half* __restrict__ INh,
      const __half* __restrict__ WA, const __half* __restrict__ WB,
      int wstride, int gbase1, int K, int cw,
      const float* __restrict__ biasA, const float* __restrict__ biasB,
      float* __restrict__ outf, __half* __restrict__ outhA, __half* __restrict__ outhB,
      const float* __restrict__ res, const float* __restrict__ gamma,
      __half* __restrict__ xh) {
    __shared__ __align__(16) __half sA[2][2][GTILES*64*40];
    __shared__ __align__(16) __half sB[2][32*72];

    const int tid = threadIdx.x, warp = tid >> 5, lane = tid & 31;
    const int g = warp >> 2, wi = warp & 3, wt = tid & 127;
    const int b = blockIdx.z, n0 = blockIdx.x * 64;
    const __half* Wg = (g ? WB : WA) + (PERBATCH ? (size_t)b*wstride : 0);
    __half* outh = g ? outhB : outhA;
    const float* biasg = g ? biasB : biasA;
    const int gbase = g ? gbase1 : 0;

    auto stageA = [&](int k0, int bf) {
        #pragma unroll
        for (int it = 0; it < GTILES*2; it++) {
            int idx = wt + it*128;
            int c = idx >> 2, ch = idx & 3;
            cpa16(smem_u32(&sA[bf][g][c*40 + ch*8]),
                  Wg + (size_t)(gbase + c)*K + k0 + ch*8);
        }
    };
    auto stageB = [&](int k0, int bf) {
        int k = tid >> 3, nseg = tid & 7;
        cpa16(smem_u32(&sB[bf][k*72 + nseg*8]),
              &INh[((size_t)b*K + k0 + k)*NPIX + n0 + nseg*8]);
    };

    float acc[GTILES][8][4] = {};

    stageA(0, 0); stageB(0, 0); CP_COMMIT();
    const int nch = K >> 5;
    for (int i = 0; i < nch; i++) {
        const int bf = i & 1;
        CP_WAIT0();
        __syncthreads();
        if (i + 1 < nch) { stageA((i+1)*32, bf^1); stageB((i+1)*32, bf^1); CP_COMMIT(); }

        #pragma unroll
        for (int ct = 0; ct < GTILES; ct++) {
            uint32_t qa[2][4];
            #pragma unroll
            for (int kc = 0; kc < 2; kc++) {
                uint32_t addr = smem_u32(&sA[bf][g][(ct*64 + wi*16 + (lane & 15))*40
                                                    + kc*16 + (lane >> 4)*8]);
                LDSM_X4(qa[kc][0], qa[kc][1], qa[kc][2], qa[kc][3], addr);
            }
            #pragma unroll
            for (int nt = 0; nt < 8; nt++) {
                uint32_t b0[2], b1[2];
                uint32_t a0 = smem_u32(&sB[bf][(lane & 15)*72 + nt*8]);
                LDSM_X2_T(b0[0], b0[1], a0);
                LDSM_X2_T(b1[0], b1[1], a0 + 16*72*2);
                MMA16816(acc[ct][nt], qa[0], b0);
                MMA16816(acc[ct][nt], qa[1], b1);
            }
        }
    }

    float s_s = 0.f, s_ss = 0.f;
    #pragma unroll
    for (int ct = 0; ct < GTILES; ct++) {
        int cA = gbase + ct*64 + wi*16 + (lane >> 2), cB = cA + 8;
        float bsA = 0.f, bsB = 0.f;
        if (HASBIAS) { bsA = biasg[b*256 + cA]; bsB = biasg[b*256 + cB]; }
        #pragma unroll
        for (int nt = 0; nt < 8; nt++) {
            int n = nt*8 + (lane & 3)*2;
            size_t oA = ((size_t)b*cw + cA)*NPIX + n0 + n;
            size_t oB = ((size_t)b*cw + cB)*NPIX + n0 + n;
            float v0 = acc[ct][nt][0] + bsA, v1 = acc[ct][nt][1] + bsA;
            float v2 = acc[ct][nt][2] + bsB, v3 = acc[ct][nt][3] + bsB;
            if constexpr (EP == 1) {
                *(uint32_t*)&outh[oA] = pack_hf2(v0, v1);
                *(uint32_t*)&outh[oB] = pack_hf2(v2, v3);
            } else if constexpr (EP == 2) {
                float gm = gamma[0];
                float2 rA = *(const float2*)&res[oA];
                float2 rB = *(const float2*)&res[oB];
                v0 = rA.x + gm*v0; v1 = rA.y + gm*v1;
                v2 = rB.x + gm*v2; v3 = rB.y + gm*v3;
                *(float2*)&outf[oA] = make_float2(v0, v1);
                *(float2*)&outf[oB] = make_float2(v2, v3);
                if (DUALX) {
                    *(uint32_t*)&xh[oA] = pack_hf2(v0, v1);
                    *(uint32_t*)&xh[oB] = pack_hf2(v2, v3);
                }
                if (DOSTATS) {
                    s_s  += (v0 + v1) + (v2 + v3);
                    s_ss += v0*v0 + v1*v1 + v2*v2 + v3*v3;
                }
            } else {
                v0 = 0.5f*v0*(1.0f + erff(v0*0.70710678118654752f));
                v1 = 0.5f*v1*(1.0f + erff(v1*0.70710678118654752f));
                v2 = 0.5f*v2*(1.0f + erff(v2*0.70710678118654752f));
                v3 = 0.5f*v3*(1.0f + erff(v3*0.70710678118654752f));
                *(uint32_t*)&outh[oA] = pack_hf2(v0, v1);
                *(uint32_t*)&outh[oB] = pack_hf2(v2, v3);
            }
        }
    }
    if constexpr (DOSTATS) {
        #pragma unroll
        for (int o = 16; o; o >>= 1) {
            s_s  += __shfl_xor_sync(0xffffffffu, s_s,  o);
            s_ss += __shfl_xor_sync(0xffffffffu, s_ss, o);
        }
        __shared__ float shr[2][8];
        if (lane == 0) { shr[0][warp] = s_s; shr[1][warp] = s_ss; }
        __syncthreads();
        if (tid == 0) {
            float S = 0.f, SS = 0.f;
            #pragma unroll
            for (int i = 0; i < 8; i++) { S += shr[0][i]; SS += shr[1][i]; }
            g_part[2][b][blockIdx.x][0] = S; g_part[2][b][blockIdx.x][1] = SS;
        }
    }
}

// ================= flash attention (fp16, exp2-domain, V-ones l-sum, 3-buf pipeline) =================
#define QSTR 136
#define KVSTR 72

__device__ __forceinline__ void prefetch_kv(__half* sk, __half* sv,
        const __half* Kb, const __half* Vb, int n0, int tid) {
    #pragma unroll
    for (int i = 0; i < 2; i++) {
        int ch = tid + i * 128;
        int row = ch >> 3, col = ch & 7;
        cpa16(smem_u32(&sk[row*KVSTR + col*8]), Kb + (size_t)row*NPIX + n0 + col*8);
    }
    #pragma unroll
    for (int i = 0; i < 2; i++) {
        int ch = tid + i * 128;
        int row = ch >> 3, col = ch & 7;
        cpa16(smem_u32(&sv[row*KVSTR + col*8]), Vb + (size_t)row*NPIX + n0 + col*8);
    }
}

__global__ void __launch_bounds__(128, 4)
flash_mma(const __half* __restrict__ Qg, const __half* __restrict__ Kg,
          const __half* __restrict__ Vg, __half* __restrict__ Og) {
    __shared__ __align__(16) __half sQT[32*QSTR];       // Q tile, later output transpose
    __shared__ __align__(16) __half sK[3][32*KVSTR];
    __shared__ __align__(16) __half sV[3][40*KVSTR];    // rows 32..39 ones/zeros

    const int tid = threadIdx.x, warp = tid >> 5, lane = tid & 31;
    const int bh = blockIdx.y, m0 = blockIdx.x * 128;
    const __half* Qb = Qg + (size_t)bh * HDIM * NPIX + m0;
    const __half* Kb = Kg + (size_t)bh * HDIM * NPIX;
    const __half* Vb = Vg + (size_t)bh * HDIM * NPIX;

    // ones rows for 3 V buffers
    #pragma unroll
    for (int i = 0; i < 2; i++) {
        int idx = tid + i*128;
        if (idx < 192) {
            int bfi = idx >> 6, rem = idx & 63;
            int row = 32 + (rem >> 3), chk = rem & 7;
            uint32_t hv = pack_hf2(row == 32 ? 1.0f : 0.0f, row == 32 ? 1.0f : 0.0f);
            uint4 q4 = make_uint4(hv, hv, hv, hv);
            *(uint4*)&sV[bfi][row*KVSTR + chk*8] = q4;
        }
    }
    // Q tile
    #pragma unroll
    for (int i = 0; i < 4; i++) {
        int ch = tid + i * 128;
        int row = ch >> 4, col = ch & 15;
        *(uint4*)&sQT[row*QSTR + col*8] = *(const uint4*)(Qb + (size_t)row*NPIX + col*8);
    }
    prefetch_kv(sK[0], sV[0], Kb, Vb, 0, tid);
    CP_COMMIT();
    prefetch_kv(sK[1], sV[1], Kb, Vb, 64, tid);
    CP_COMMIT();

    uint32_t qa[2][2][4];
    float Oc[2][5][4] = {};

    for (int nb = 0; nb < 64; nb++) {
        const int buf = nb % 3;
        CP_WAIT1();                 // all but newest group done -> tile nb resident
        __syncthreads();
        if (nb == 0) {
            #pragma unroll
            for (int mb = 0; mb < 2; mb++)
                #pragma unroll
                for (int kc = 0; kc < 2; kc++) {
                    uint32_t addr = smem_u32(&sQT[(kc*16 + ((lane >> 4) & 1)*8 + (lane & 7))*QSTR
                                                  + warp*32 + mb*16 + ((lane >> 3) & 1)*8]);
                    LDSM_X4_T(qa[mb][kc][0], qa[mb][kc][1], qa[mb][kc][2], qa[mb][kc][3], addr);
                }
        }
        if (nb + 2 < 64)
            prefetch_kv(sK[(nb+2)%3], sV[(nb+2)%3], Kb, Vb, (nb+2)*64, tid);
        CP_COMMIT();                // always commit (possibly empty group)

        // ---- S = Q K^T fused with EX2 -> P fragments ----
        uint32_t pa[2][4][4];
        #pragma unroll
        for (int nt = 0; nt < 8; nt++) {
            uint32_t bk0[2], bk1[2];
            uint32_t a0 = smem_u32(&sK[buf][(lane & 15)*KVSTR + nt*8]);
            LDSM_X2_T(bk0[0], bk0[1], a0);
            LDSM_X2_T(bk1[0], bk1[1], a0 + 16*KVSTR*2);
            #pragma unroll
            for (int mb = 0; mb < 2; mb++) {
                float S[4] = {0.f, 0.f, 0.f, 0.f};
                MMA16816(S, qa[mb][0], bk0);
                MMA16816(S, qa[mb][1], bk1);
                uint32_t e01, e23;
                EX2_F16X2(e01, pack_hf2(S[0], S[1]));
                EX2_F16X2(e23, pack_hf2(S[2], S[3]));
                pa[mb][nt >> 1][(nt & 1)*2 + 0] = e01;
                pa[mb][nt >> 1][(nt & 1)*2 + 1] = e23;
            }
        }

        // ---- O += P V  (dt=4 -> ones rows -> l in col 32) ----
        #pragma unroll
        for (int kc = 0; kc < 4; kc++)
            #pragma unroll
            for (int dt = 0; dt < 5; dt++) {
                uint32_t vb[2];
                uint32_t addr = smem_u32(&sV[buf][(dt*8 + (lane & 7))*KVSTR
                                                  + kc*16 + ((lane >> 3) & 1)*8]);
                LDSM_X2(vb[0], vb[1], addr);
                MMA16816(Oc[0][dt], pa[0][kc], vb);
                MMA16816(Oc[1][dt], pa[1][kc], vb);
            }
    }

    float inv[2][2];
    #pragma unroll
    for (int mb = 0; mb < 2; mb++) {
        float l0 = __shfl_sync(0xffffffffu, Oc[mb][4][0], lane & 28);
        float l1 = __shfl_sync(0xffffffffu, Oc[mb][4][2], lane & 28);
        inv[mb][0] = 1.0f / l0;
        inv[mb][1] = 1.0f / l1;
    }

    // epilogue: fp16 transpose through sQT (aliased), write ao [b][c][n]
    __syncthreads();
    #pragma unroll
    for (int mb = 0; mb < 2; mb++) {
        int r = warp*32 + mb*16 + (lane >> 2);
        #pragma unroll
        for (int dt = 0; dt < 4; dt++) {
            int d = dt*8 + (lane & 3)*2;
            sQT[(d+0)*QSTR + r    ] = __float2half(Oc[mb][dt][0]*inv[mb][0]);
            sQT[(d+1)*QSTR + r    ] = __float2half(Oc[mb][dt][1]*inv[mb][0]);
            sQT[(d+0)*QSTR + r + 8] = __float2half(Oc[mb][dt][2]*inv[mb][1]);
            sQT[(d+1)*QSTR + r + 8] = __float2half(Oc[mb][dt][3]*inv[mb][1]);
        }
    }
    __syncthreads();
    __half* aob = Og + (size_t)bh * HDIM * NPIX + m0;
    #pragma unroll
    for (int i = 0; i < 4; i++) {
        int idx = tid + i*128;
        int d = idx >> 4, seg = idx & 15;
        *(uint4*)(aob + (size_t)d*NPIX + seg*8) = *(const uint4*)&sQT[d*QSTR + seg*8];
    }
}

// ================= launch =================
extern "C" void kernel_launch(void* const* d_in, const int* in_sizes, int n_in,
                              void* d_out, int out_size) {
    const float* high  = (const float*)d_in[0];
    const float* low   = (const float*)d_in[1];
    const float* nhw   = (const float*)d_in[2];
    const float* nhb   = (const float*)d_in[3];
    const float* nlw   = (const float*)d_in[4];
    const float* nlb   = (const float*)d_in[5];
    const float* nfw   = (const float*)d_in[6];
    const float* nfb   = (const float*)d_in[7];
    const float* Wq    = (const float*)d_in[8];
    const float* Wk    = (const float*)d_in[9];
    const float* Wv    = (const float*)d_in[10];
    const float* Wproj = (const float*)d_in[11];
    const float* Wffn1 = (const float*)d_in[12];
    const float* Wffn2 = (const float*)d_in[13];
    const float* ga    = (const float*)d_in[14];
    const float* gf    = (const float*)d_in[15];
    float* out = (float*)d_out;

    float *x, *bias;
    __half *hh, *lh, *q, *k, *v, *ao, *xh, *mid, *whq, *whk, *whv, *whp, *wh1, *wh2;
    cudaGetSymbolAddress((void**)&hh,  g_hh);
    cudaGetSymbolAddress((void**)&lh,  g_lh);
    cudaGetSymbolAddress((void**)&q,   g_q);
    cudaGetSymbolAddress((void**)&k,   g_k);
    cudaGetSymbolAddress((void**)&v,   g_v);
    cudaGetSymbolAddress((void**)&ao,  g_ao);
    cudaGetSymbolAddress((void**)&x,   g_x);
    cudaGetSymbolAddress((void**)&xh,  g_xh);
    cudaGetSymbolAddress((void**)&mid, g_mid);
    cudaGetSymbolAddress((void**)&whq, g_whq);
    cudaGetSymbolAddress((void**)&whk, g_whk);
    cudaGetSymbolAddress((void**)&whv, g_whv);
    cudaGetSymbolAddress((void**)&whp, g_whp);
    cudaGetSymbolAddress((void**)&wh1, g_wh1);
    cudaGetSymbolAddress((void**)&wh2, g_wh2);
    cudaGetSymbolAddress((void**)&bias, g_bias);
    const float* bq = bias + 0*BATCH*256;
    const float* bk = bias + 1*BATCH*256;
    const float* bv = bias + 2*BATCH*256;
    const float* b1 = bias + 3*BATCH*256;

    const float scale = 0.17677669529663687f * 1.44269504088896340736f; // 1/sqrt(32)*log2e
    dim3 gg(NPIX/64, 1, BATCH);

    stats_partial2<<<dim3(BATCH, 32, 2), 256>>>(high, low);
    convert_inputs<<<dim3(4096, 2), 256>>>(high, low);
    stats_final<<<dim3(BATCH, 2), 32>>>(0, (float)(CHIGH*NPIX), (float)(CLOW*NPIX), 32);
    fold_qkvp<<<dim3(BATCH, 5), 128>>>(Wq, Wk, Wv, Wproj, Wffn2, nhw, nhb, nlw, nlb, scale);

    gemm2<1,1,1,1,0,0><<<gg, 256>>>(hh, whq, whq, CLOW*CHIGH, 64, CHIGH, CLOW,
                                    bq, bq, nullptr, q, q, nullptr, nullptr, nullptr);
    gemm2<1,2,1,1,0,0><<<gg, 256>>>(lh, whk, whv, CLOW*CLOW, 0, CLOW, CLOW,
                                    bk, bv, nullptr, k, v, nullptr, nullptr, nullptr);

    flash_mma<<<dim3(NPIX/128, BATCH*HEADS), 128>>>(q, k, v, ao);

    gemm2<2,1,0,0,1,1><<<gg, 256>>>(ao, whp, whp, 0, 64, CLOW, CLOW,
                                    nullptr, nullptr, x, nullptr, nullptr, low, ga, xh);
    stats_final<<<dim3(BATCH, 1), 32>>>(2, (float)(CLOW*NPIX), (float)(CLOW*NPIX), 64);
    fold_ffn1<<<BATCH, 256>>>(Wffn1, nfw, nfb);

    gemm2<3,2,1,1,0,0><<<gg, 256>>>(xh, wh1, wh1, FFN*CLOW, 128, CLOW, FFN,
                                    b1, b1, nullptr, mid, mid, nullptr, nullptr, nullptr);
    gemm2<2,1,0,0,0,0><<<gg, 256>>>(mid, wh2, wh2, 0, 64, FFN, CLOW,
                                    nullptr, nullptr, out, nullptr, nullptr, x, gf, nullptr);

    (void)in_sizes; (void)n_in; (void)out_size;
}

// round 9
// speedup vs baseline: 1.5935x; 1.5935x over previous
#include <cuda_runtime.h>
#include <cuda_fp16.h>
#include <math.h>
#include <stdint.h>

#define BATCH 4
#define NPIX  4096
#define CHIGH 256
#define CLOW  128
#define HEADS 4
#define HDIM  32
#define FFN   256

// ======================= helpers =======================
__device__ __forceinline__ uint32_t smem_u32(const void* p) {
    uint32_t a;
    asm("{ .reg .u64 t; cvta.to.shared.u64 t, %1; cvt.u32.u64 %0, t; }" : "=r"(a) : "l"(p));
    return a;
}

#define LDSM_X4(r0, r1, r2, r3, addr) \
    asm volatile("ldmatrix.sync.aligned.m8n8.x4.shared.b16 {%0,%1,%2,%3}, [%4];" \
        : "=r"(r0), "=r"(r1), "=r"(r2), "=r"(r3) : "r"(addr))
#define LDSM_X2(r0, r1, addr) \
    asm volatile("ldmatrix.sync.aligned.m8n8.x2.shared.b16 {%0,%1}, [%2];" \
        : "=r"(r0), "=r"(r1) : "r"(addr))
#define LDSM_X4_T(r0, r1, r2, r3, addr) \
    asm volatile("ldmatrix.sync.aligned.m8n8.x4.trans.shared.b16 {%0,%1,%2,%3}, [%4];" \
        : "=r"(r0), "=r"(r1), "=r"(r2), "=r"(r3) : "r"(addr))
#define LDSM_X2_T(r0, r1, addr) \
    asm volatile("ldmatrix.sync.aligned.m8n8.x2.trans.shared.b16 {%0,%1}, [%2];" \
        : "=r"(r0), "=r"(r1) : "r"(addr))
#define MMA16816(c, a, b) \
    asm volatile("mma.sync.aligned.m16n8k16.row.col.f32.f16.f16.f32 " \
        "{%0,%1,%2,%3}, {%4,%5,%6,%7}, {%8,%9}, {%0,%1,%2,%3};" \
        : "+f"((c)[0]), "+f"((c)[1]), "+f"((c)[2]), "+f"((c)[3]) \
        : "r"((a)[0]), "r"((a)[1]), "r"((a)[2]), "r"((a)[3]), "r"((b)[0]), "r"((b)[1]))
#define EX2_F16X2(out, in) \
    asm("ex2.approx.f16x2 %0, %1;" : "=r"(out) : "r"(in))

__device__ __forceinline__ void cpa16(uint32_t dst, const void* src) {
    asm volatile("cp.async.ca.shared.global [%0], [%1], 16;" :: "r"(dst), "l"(src));
}
#define CP_COMMIT() asm volatile("cp.async.commit_group;" ::: "memory")
#define CP_WAIT0()  asm volatile("cp.async.wait_group 0;" ::: "memory")
#define CP_WAIT1()  asm volatile("cp.async.wait_group 1;" ::: "memory")

__device__ __forceinline__ uint32_t pack_hf2(float a, float b) {
    __half2 h = __floats2half2_rn(a, b);
    return *(uint32_t*)&h;
}

// ======================= scratch =======================
__device__ __half g_hn [BATCH*CHIGH*NPIX];   // groupnorm(high) fp16
__device__ __half g_ln [BATCH*CLOW *NPIX];   // groupnorm(low) fp16
__device__ __half g_q  [BATCH*CLOW *NPIX];   // [b][c][n]
__device__ __half g_k  [BATCH*CLOW *NPIX];
__device__ __half g_v  [BATCH*CLOW *NPIX];
__device__ __half g_ao [BATCH*CLOW *NPIX];
__device__ float  g_x  [BATCH*CLOW *NPIX];
__device__ __half g_xn [BATCH*CLOW *NPIX];   // norm(x) fp16
__device__ __half g_mid[BATCH*FFN  *NPIX];
__device__ float g_part[3][BATCH][64][2];
__device__ float g_mu[3][BATCH];
__device__ float g_rs[3][BATCH];
// fp16 weights (converted once)
__device__ __half g_whq[CLOW*CHIGH];
__device__ __half g_whk[CLOW*CLOW];
__device__ __half g_whv[CLOW*CLOW];
__device__ __half g_whp[CLOW*CLOW];
__device__ __half g_wh1[FFN*CLOW];
__device__ __half g_wh2[CLOW*FFN];

// ================= weight convert (fp32 -> fp16, scale folded into Wq) =================
__global__ void convert_weights(const float* __restrict__ Wq, const float* __restrict__ Wk,
                                const float* __restrict__ Wv, const float* __restrict__ Wp,
                                const float* __restrict__ W1, const float* __restrict__ W2,
                                float qscale) {
    int which = blockIdx.y;
    const float* src; __half* dst; int n; float a = 1.0f;
    switch (which) {
        case 0: src = Wq; dst = g_whq; n = CLOW*CHIGH; a = qscale; break;
        case 1: src = Wk; dst = g_whk; n = CLOW*CLOW;  break;
        case 2: src = Wv; dst = g_whv; n = CLOW*CLOW;  break;
        case 3: src = Wp; dst = g_whp; n = CLOW*CLOW;  break;
        case 4: src = W1; dst = g_wh1; n = FFN*CLOW;   break;
        default: src = W2; dst = g_wh2; n = CLOW*FFN;  break;
    }
    int i = (blockIdx.x * blockDim.x + threadIdx.x) * 4;
    if (i < n) {
        float4 v = *(const float4*)(src + i);
        uint2 p; p.x = pack_hf2(v.x*a, v.y*a); p.y = pack_hf2(v.z*a, v.w*a);
        *(uint2*)(dst + i) = p;
    }
}

// ================= GroupNorm stats (deterministic 2-stage) =================
__global__ void stats_partial2(const float* __restrict__ high, const float* __restrict__ low) {
    int b = blockIdx.x, ch = blockIdx.y, z = blockIdx.z;
    int perSample = z ? CLOW*NPIX : CHIGH*NPIX;
    int perChunk  = perSample / 32;
    const float* p = (z ? low : high) + (size_t)b*perSample + (size_t)ch*perChunk;
    float s = 0.f, ss = 0.f;
    for (int i = threadIdx.x*4; i < perChunk; i += blockDim.x*4) {
        float4 v = *(const float4*)(p + i);
        s  += v.x + v.y + v.z + v.w;
        ss += v.x*v.x + v.y*v.y + v.z*v.z + v.w*v.w;
    }
    #pragma unroll
    for (int o = 16; o; o >>= 1) {
        s  += __shfl_xor_sync(0xffffffffu, s,  o);
        ss += __shfl_xor_sync(0xffffffffu, ss, o);
    }
    __shared__ float sh[2][8];
    int w = threadIdx.x >> 5;
    if ((threadIdx.x & 31) == 0) { sh[0][w] = s; sh[1][w] = ss; }
    __syncthreads();
    if (threadIdx.x == 0) {
        float S = 0.f, SS = 0.f;
        #pragma unroll
        for (int i = 0; i < 8; i++) { S += sh[0][i]; SS += sh[1][i]; }
        g_part[z][b][ch][0] = S; g_part[z][b][ch][1] = SS;
    }
}

__global__ void stats_final(int base, float cnt0, float cnt1, int nch) {
    int b = blockIdx.x, idx = base + blockIdx.y, t = threadIdx.x;
    float cnt = blockIdx.y ? cnt1 : cnt0;
    float s = g_part[idx][b][t][0], ss = g_part[idx][b][t][1];
    if (nch > 32) { s += g_part[idx][b][t+32][0]; ss += g_part[idx][b][t+32][1]; }
    #pragma unroll
    for (int o = 16; o; o >>= 1) {
        s  += __shfl_xor_sync(0xffffffffu, s,  o);
        ss += __shfl_xor_sync(0xffffffffu, ss, o);
    }
    if (t == 0) {
        float mu = s / cnt;
        float var = ss / cnt - mu * mu;
        g_mu[idx][b] = mu;
        g_rs[idx][b] = rsqrtf(var + 1e-5f);
    }
}

// ================= normalize + convert to fp16 =================
// z=0: high (C=256, set 0) -> g_hn; z=1: low (C=128, set 1) -> g_ln
__global__ void norm_inputs(const float* __restrict__ high, const float* __restrict__ low,
                            const float* __restrict__ nhw, const float* __restrict__ nhb,
                            const float* __restrict__ nlw, const float* __restrict__ nlb) {
    int z = blockIdx.y;
    int C = z ? CLOW : CHIGH;
    const float* src = z ? low : high;
    const float* w   = z ? nlw : nhw;
    const float* bb  = z ? nlb : nhb;
    __half* dst = z ? g_ln : g_hn;
    int n = BATCH * C * NPIX;
    int i = (blockIdx.x * 256 + threadIdx.x) * 4;
    if (i >= n) return;
    int b = i / (C * NPIX);
    int c = (i >> 12) % C;                 // NPIX = 4096
    float mu = g_mu[z][b], rs = g_rs[z][b];
    float sw = w[c] * rs, sb = bb[c] - mu * sw;
    float4 v = *(const float4*)(src + i);
    uint2 p;
    p.x = pack_hf2(v.x*sw + sb, v.y*sw + sb);
    p.y = pack_hf2(v.z*sw + sb, v.w*sw + sb);
    *(uint2*)(dst + i) = p;
}

__global__ void norm_x(const float* __restrict__ nfw, const float* __restrict__ nfb) {
    int i = (blockIdx.x * 256 + threadIdx.x) * 4;
    int b = i / (CLOW * NPIX);
    int c = (i >> 12) % CLOW;
    float mu = g_mu[2][b], rs = g_rs[2][b];
    float sw = nfw[c] * rs, sb = nfb[c] - mu * sw;
    float4 v = *(const float4*)(g_x + i);
    uint2 p;
    p.x = pack_hf2(v.x*sw + sb, v.y*sw + sb);
    p.y = pack_hf2(v.z*sw + sb, v.w*sw + sb);
    *(uint2*)(g_xn + i) = p;
}

// ================= dual-warpgroup TC GEMM, all-fp16 cp.async =================
// EP: 1 = f16 out; 2 = fp32 out = res + gamma*acc (+stats); 3 = gelu -> f16
template<int EP, int GTILES, int DOSTATS>
__global__ void __launch_bounds__(256, 2)
gemm2(const __half* __restrict__ INh,
      const __half* __restrict__ WA, const __half* __restrict__ WB,
      int gbase1, int K, int cw,
      float* __restrict__ outf, __half* __restrict__ outhA, __half* __restrict__ outhB,
      const float* __restrict__ res, const float* __restrict__ gamma) {
    __shared__ __align__(16) __half sA[2][2][GTILES*64*40];
    __shared__ __align__(16) __half sB[2][32*72];

    const int tid = threadIdx.x, warp = tid >> 5, lane = tid & 31;
    const int g = warp >> 2, wi = warp & 3, wt = tid & 127;
    const int b = blockIdx.z, n0 = blockIdx.x * 64;
    const __half* Wg = g ? WB : WA;
    __half* outh = g ? outhB : outhA;
    const int gbase = g ? gbase1 : 0;

    auto stageA = [&](int k0, int bf) {
        #pragma unroll
        for (int it = 0; it < GTILES*2; it++) {
            int idx = wt + it*128;
            int c = idx >> 2, ch = idx & 3;
            cpa16(smem_u32(&sA[bf][g][c*40 + ch*8]),
                  Wg + (size_t)(gbase + c)*K + k0 + ch*8);
        }
    };
    auto stageB = [&](int k0, int bf) {
        int k = tid >> 3, nseg = tid & 7;
        cpa16(smem_u32(&sB[bf][k*72 + nseg*8]),
              &INh[((size_t)b*K + k0 + k)*NPIX + n0 + nseg*8]);
    };

    float acc[GTILES][8][4] = {};

    stageA(0, 0); stageB(0, 0); CP_COMMIT();
    const int nch = K >> 5;
    for (int i = 0; i < nch; i++) {
        const int bf = i & 1;
        CP_WAIT0();
        __syncthreads();
        if (i + 1 < nch) { stageA((i+1)*32, bf^1); stageB((i+1)*32, bf^1); CP_COMMIT(); }

        #pragma unroll
        for (int ct = 0; ct < GTILES; ct++) {
            uint32_t qa[2][4];
            #pragma unroll
            for (int kc = 0; kc < 2; kc++) {
                uint32_t addr = smem_u32(&sA[bf][g][(ct*64 + wi*16 + (lane & 15))*40
                                                    + kc*16 + (lane >> 4)*8]);
                LDSM_X4(qa[kc][0], qa[kc][1], qa[kc][2], qa[kc][3], addr);
            }
            #pragma unroll
            for (int nt = 0; nt < 8; nt++) {
                uint32_t b0[2], b1[2];
                uint32_t a0 = smem_u32(&sB[bf][(lane & 15)*72 + nt*8]);
                LDSM_X2_T(b0[0], b0[1], a0);
                LDSM_X2_T(b1[0], b1[1], a0 + 16*72*2);
                MMA16816(acc[ct][nt], qa[0], b0);
                MMA16816(acc[ct][nt], qa[1], b1);
            }
        }
    }

    float s_s = 0.f, s_ss = 0.f;
    #pragma unroll
    for (int ct = 0; ct < GTILES; ct++) {
        int cA = gbase + ct*64 + wi*16 + (lane >> 2), cB = cA + 8;
        #pragma unroll
        for (int nt = 0; nt < 8; nt++) {
            int n = nt*8 + (lane & 3)*2;
            size_t oA = ((size_t)b*cw + cA)*NPIX + n0 + n;
            size_t oB = ((size_t)b*cw + cB)*NPIX + n0 + n;
            float v0 = acc[ct][nt][0], v1 = acc[ct][nt][1];
            float v2 = acc[ct][nt][2], v3 = acc[ct][nt][3];
            if constexpr (EP == 1) {
                *(uint32_t*)&outh[oA] = pack_hf2(v0, v1);
                *(uint32_t*)&outh[oB] = pack_hf2(v2, v3);
            } else if constexpr (EP == 2) {
                float gm = gamma[0];
                float2 rA = *(const float2*)&res[oA];
                float2 rB = *(const float2*)&res[oB];
                v0 = rA.x + gm*v0; v1 = rA.y + gm*v1;
                v2 = rB.x + gm*v2; v3 = rB.y + gm*v3;
                *(float2*)&outf[oA] = make_float2(v0, v1);
                *(float2*)&outf[oB] = make_float2(v2, v3);
                if (DOSTATS) {
                    s_s  += (v0 + v1) + (v2 + v3);
                    s_ss += v0*v0 + v1*v1 + v2*v2 + v3*v3;
                }
            } else {
                v0 = 0.5f*v0*(1.0f + erff(v0*0.70710678118654752f));
                v1 = 0.5f*v1*(1.0f + erff(v1*0.70710678118654752f));
                v2 = 0.5f*v2*(1.0f + erff(v2*0.70710678118654752f));
                v3 = 0.5f*v3*(1.0f + erff(v3*0.70710678118654752f));
                *(uint32_t*)&outh[oA] = pack_hf2(v0, v1);
                *(uint32_t*)&outh[oB] = pack_hf2(v2, v3);
            }
        }
    }
    if constexpr (DOSTATS) {
        #pragma unroll
        for (int o = 16; o; o >>= 1) {
            s_s  += __shfl_xor_sync(0xffffffffu, s_s,  o);
            s_ss += __shfl_xor_sync(0xffffffffu, s_ss, o);
        }
        __shared__ float shr[2][8];
        if (lane == 0) { shr[0][warp] = s_s; shr[1][warp] = s_ss; }
        __syncthreads();
        if (tid == 0) {
            float S = 0.f, SS = 0.f;
            #pragma unroll
            for (int i = 0; i < 8; i++) { S += shr[0][i]; SS += shr[1][i]; }
            g_part[2][b][blockIdx.x][0] = S; g_part[2][b][blockIdx.x][1] = SS;
        }
    }
}

// ================= flash attention (fp16, exp2-domain, V-ones l-sum, 3-buf pipeline) =================
#define QSTR 136
#define KVSTR 72

__device__ __forceinline__ void prefetch_kv(__half* sk, __half* sv,
        const __half* Kb, const __half* Vb, int n0, int tid) {
    #pragma unroll
    for (int i = 0; i < 2; i++) {
        int ch = tid + i * 128;
        int row = ch >> 3, col = ch & 7;
        cpa16(smem_u32(&sk[row*KVSTR + col*8]), Kb + (size_t)row*NPIX + n0 + col*8);
    }
    #pragma unroll
    for (int i = 0; i < 2; i++) {
        int ch = tid + i * 128;
        int row = ch >> 3, col = ch & 7;
        cpa16(smem_u32(&sv[row*KVSTR + col*8]), Vb + (size_t)row*NPIX + n0 + col*8);
    }
}

__global__ void __launch_bounds__(128, 4)
flash_mma(const __half* __restrict__ Qg, const __half* __restrict__ Kg,
          const __half* __restrict__ Vg, __half* __restrict__ Og) {
    __shared__ __align__(16) __half sQT[32*QSTR];       // Q tile, later output transpose
    __shared__ __align__(16) __half sK[3][32*KVSTR];
    __shared__ __align__(16) __half sV[3][40*KVSTR];    // rows 32..39 ones/zeros

    const int tid = threadIdx.x, warp = tid >> 5, lane = tid & 31;
    const int bh = blockIdx.y, m0 = blockIdx.x * 128;
    const __half* Qb = Qg + (size_t)bh * HDIM * NPIX + m0;
    const __half* Kb = Kg + (size_t)bh * HDIM * NPIX;
    const __half* Vb = Vg + (size_t)bh * HDIM * NPIX;

    #pragma unroll
    for (int i = 0; i < 2; i++) {
        int idx = tid + i*128;
        if (idx < 192) {
            int bfi = idx >> 6, rem = idx & 63;
            int row = 32 + (rem >> 3), chk = rem & 7;
            uint32_t hv = pack_hf2(row == 32 ? 1.0f : 0.0f, row == 32 ? 1.0f : 0.0f);
            uint4 q4 = make_uint4(hv, hv, hv, hv);
            *(uint4*)&sV[bfi][row*KVSTR + chk*8] = q4;
        }
    }
    #pragma unroll
    for (int i = 0; i < 4; i++) {
        int ch = tid + i * 128;
        int row = ch >> 4, col = ch & 15;
        *(uint4*)&sQT[row*QSTR + col*8] = *(const uint4*)(Qb + (size_t)row*NPIX + col*8);
    }
    prefetch_kv(sK[0], sV[0], Kb, Vb, 0, tid);
    CP_COMMIT();
    prefetch_kv(sK[1], sV[1], Kb, Vb, 64, tid);
    CP_COMMIT();

    uint32_t qa[2][2][4];
    float Oc[2][5][4] = {};

    for (int nb = 0; nb < 64; nb++) {
        const int buf = nb % 3;
        CP_WAIT1();
        __syncthreads();
        if (nb == 0) {
            #pragma unroll
            for (int mb = 0; mb < 2; mb++)
                #pragma unroll
                for (int kc = 0; kc < 2; kc++) {
                    uint32_t addr = smem_u32(&sQT[(kc*16 + ((lane >> 4) & 1)*8 + (lane & 7))*QSTR
                                                  + warp*32 + mb*16 + ((lane >> 3) & 1)*8]);
                    LDSM_X4_T(qa[mb][kc][0], qa[mb][kc][1], qa[mb][kc][2], qa[mb][kc][3], addr);
                }
        }
        if (nb + 2 < 64)
            prefetch_kv(sK[(nb+2)%3], sV[(nb+2)%3], Kb, Vb, (nb+2)*64, tid);
        CP_COMMIT();

        uint32_t pa[2][4][4];
        #pragma unroll
        for (int nt = 0; nt < 8; nt++) {
            uint32_t bk0[2], bk1[2];
            uint32_t a0 = smem_u32(&sK[buf][(lane & 15)*KVSTR + nt*8]);
            LDSM_X2_T(bk0[0], bk0[1], a0);
            LDSM_X2_T(bk1[0], bk1[1], a0 + 16*KVSTR*2);
            #pragma unroll
            for (int mb = 0; mb < 2; mb++) {
                float S[4] = {0.f, 0.f, 0.f, 0.f};
                MMA16816(S, qa[mb][0], bk0);
                MMA16816(S, qa[mb][1], bk1);
                uint32_t e01, e23;
                EX2_F16X2(e01, pack_hf2(S[0], S[1]));
                EX2_F16X2(e23, pack_hf2(S[2], S[3]));
                pa[mb][nt >> 1][(nt & 1)*2 + 0] = e01;
                pa[mb][nt >> 1][(nt & 1)*2 + 1] = e23;
            }
        }

        #pragma unroll
        for (int kc = 0; kc < 4; kc++)
            #pragma unroll
            for (int dt = 0; dt < 5; dt++) {
                uint32_t vb[2];
                uint32_t addr = smem_u32(&sV[buf][(dt*8 + (lane & 7))*KVSTR
                                                  + kc*16 + ((lane >> 3) & 1)*8]);
                LDSM_X2(vb[0], vb[1], addr);
                MMA16816(Oc[0][dt], pa[0][kc], vb);
                MMA16816(Oc[1][dt], pa[1][kc], vb);
            }
    }

    float inv[2][2];
    #pragma unroll
    for (int mb = 0; mb < 2; mb++) {
        float l0 = __shfl_sync(0xffffffffu, Oc[mb][4][0], lane & 28);
        float l1 = __shfl_sync(0xffffffffu, Oc[mb][4][2], lane & 28);
        inv[mb][0] = 1.0f / l0;
        inv[mb][1] = 1.0f / l1;
    }

    __syncthreads();
    #pragma unroll
    for (int mb = 0; mb < 2; mb++) {
        int r = warp*32 + mb*16 + (lane >> 2);
        #pragma unroll
        for (int dt = 0; dt < 4; dt++) {
            int d = dt*8 + (lane & 3)*2;
            sQT[(d+0)*QSTR + r    ] = __float2half(Oc[mb][dt][0]*inv[mb][0]);
            sQT[(d+1)*QSTR + r    ] = __float2half(Oc[mb][dt][1]*inv[mb][0]);
            sQT[(d+0)*QSTR + r + 8] = __float2half(Oc[mb][dt][2]*inv[mb][1]);
            sQT[(d+1)*QSTR + r + 8] = __float2half(Oc[mb][dt][3]*inv[mb][1]);
        }
    }
    __syncthreads();
    __half* aob = Og + (size_t)bh * HDIM * NPIX + m0;
    #pragma unroll
    for (int i = 0; i < 4; i++) {
        int idx = tid + i*128;
        int d = idx >> 4, seg = idx & 15;
        *(uint4*)(aob + (size_t)d*NPIX + seg*8) = *(const uint4*)&sQT[d*QSTR + seg*8];
    }
}

// ================= launch =================
extern "C" void kernel_launch(void* const* d_in, const int* in_sizes, int n_in,
                              void* d_out, int out_size) {
    const float* high  = (const float*)d_in[0];
    const float* low   = (const float*)d_in[1];
    const float* nhw   = (const float*)d_in[2];
    const float* nhb   = (const float*)d_in[3];
    const float* nlw   = (const float*)d_in[4];
    const float* nlb   = (const float*)d_in[5];
    const float* nfw   = (const float*)d_in[6];
    const float* nfb   = (const float*)d_in[7];
    const float* Wq    = (const float*)d_in[8];
    const float* Wk    = (const float*)d_in[9];
    const float* Wv    = (const float*)d_in[10];
    const float* Wproj = (const float*)d_in[11];
    const float* Wffn1 = (const float*)d_in[12];
    const float* Wffn2 = (const float*)d_in[13];
    const float* ga    = (const float*)d_in[14];
    const float* gf    = (const float*)d_in[15];
    float* out = (float*)d_out;

    float *x;
    __half *hn, *ln, *q, *k, *v, *ao, *xn, *mid, *whq, *whk, *whv, *whp, *wh1, *wh2;
    cudaGetSymbolAddress((void**)&hn,  g_hn);
    cudaGetSymbolAddress((void**)&ln,  g_ln);
    cudaGetSymbolAddress((void**)&q,   g_q);
    cudaGetSymbolAddress((void**)&k,   g_k);
    cudaGetSymbolAddress((void**)&v,   g_v);
    cudaGetSymbolAddress((void**)&ao,  g_ao);
    cudaGetSymbolAddress((void**)&x,   g_x);
    cudaGetSymbolAddress((void**)&xn,  g_xn);
    cudaGetSymbolAddress((void**)&mid, g_mid);
    cudaGetSymbolAddress((void**)&whq, g_whq);
    cudaGetSymbolAddress((void**)&whk, g_whk);
    cudaGetSymbolAddress((void**)&whv, g_whv);
    cudaGetSymbolAddress((void**)&whp, g_whp);
    cudaGetSymbolAddress((void**)&wh1, g_wh1);
    cudaGetSymbolAddress((void**)&wh2, g_wh2);

    const float scale = 0.17677669529663687f * 1.44269504088896340736f; // 1/sqrt(32)*log2e
    dim3 gg(NPIX/64, 1, BATCH);

    convert_weights<<<dim3(32, 6), 256>>>(Wq, Wk, Wv, Wproj, Wffn1, Wffn2, scale);
    stats_partial2<<<dim3(BATCH, 32, 2), 256>>>(high, low);
    stats_final<<<dim3(BATCH, 2), 32>>>(0, (float)(CHIGH*NPIX), (float)(CLOW*NPIX), 32);
    norm_inputs<<<dim3(4096, 2), 256>>>(high, low, nhw, nhb, nlw, nlb);

    gemm2<1,1,0><<<gg, 256>>>(hn, whq, whq, 64, CHIGH, CLOW,
                              nullptr, q, q, nullptr, nullptr);
    gemm2<1,2,0><<<gg, 256>>>(ln, whk, whv, 0, CLOW, CLOW,
                              nullptr, k, v, nullptr, nullptr);

    flash_mma<<<dim3(NPIX/128, BATCH*HEADS), 128>>>(q, k, v, ao);

    gemm2<2,1,1><<<gg, 256>>>(ao, whp, whp, 64, CLOW, CLOW,
                              x, nullptr, nullptr, low, ga);
    stats_final<<<dim3(BATCH, 1), 32>>>(2, (float)(CLOW*NPIX), (float)(CLOW*NPIX), 64);
    norm_x<<<2048, 256>>>(nfw, nfb);

    gemm2<3,2,0><<<gg, 256>>>(xn, wh1, wh1, 128, CLOW, FFN,
                              nullptr, mid, mid, nullptr, nullptr);
    gemm2<2,1,0><<<gg, 256>>>(mid, wh2, wh2, 64, FFN, CLOW,
                              out, nullptr, nullptr, x, gf);

    (void)in_sizes; (void)n_in; (void)out_size;
}

// round 10
// speedup vs baseline: 1.7575x; 1.1029x over previous
#include <cuda_runtime.h>
#include <cuda_fp16.h>
#include <math.h>
#include <stdint.h>

#define BATCH 4
#define NPIX  4096
#define CHIGH 256
#define CLOW  128
#define HEADS 4
#define HDIM  32
#define FFN   256

// ======================= helpers =======================
__device__ __forceinline__ uint32_t smem_u32(const void* p) {
    uint32_t a;
    asm("{ .reg .u64 t; cvta.to.shared.u64 t, %1; cvt.u32.u64 %0, t; }" : "=r"(a) : "l"(p));
    return a;
}

#define LDSM_X4(r0, r1, r2, r3, addr) \
    asm volatile("ldmatrix.sync.aligned.m8n8.x4.shared.b16 {%0,%1,%2,%3}, [%4];" \
        : "=r"(r0), "=r"(r1), "=r"(r2), "=r"(r3) : "r"(addr))
#define LDSM_X2(r0, r1, addr) \
    asm volatile("ldmatrix.sync.aligned.m8n8.x2.shared.b16 {%0,%1}, [%2];" \
        : "=r"(r0), "=r"(r1) : "r"(addr))
#define LDSM_X4_T(r0, r1, r2, r3, addr) \
    asm volatile("ldmatrix.sync.aligned.m8n8.x4.trans.shared.b16 {%0,%1,%2,%3}, [%4];" \
        : "=r"(r0), "=r"(r1), "=r"(r2), "=r"(r3) : "r"(addr))
#define LDSM_X2_T(r0, r1, addr) \
    asm volatile("ldmatrix.sync.aligned.m8n8.x2.trans.shared.b16 {%0,%1}, [%2];" \
        : "=r"(r0), "=r"(r1) : "r"(addr))
#define MMA16816(c, a, b) \
    asm volatile("mma.sync.aligned.m16n8k16.row.col.f32.f16.f16.f32 " \
        "{%0,%1,%2,%3}, {%4,%5,%6,%7}, {%8,%9}, {%0,%1,%2,%3};" \
        : "+f"((c)[0]), "+f"((c)[1]), "+f"((c)[2]), "+f"((c)[3]) \
        : "r"((a)[0]), "r"((a)[1]), "r"((a)[2]), "r"((a)[3]), "r"((b)[0]), "r"((b)[1]))
#define MMA16816H(c, a, b) \
    asm volatile("mma.sync.aligned.m16n8k16.row.col.f16.f16.f16.f16 " \
        "{%0,%1}, {%2,%3,%4,%5}, {%6,%7}, {%0,%1};" \
        : "+r"((c)[0]), "+r"((c)[1]) \
        : "r"((a)[0]), "r"((a)[1]), "r"((a)[2]), "r"((a)[3]), "r"((b)[0]), "r"((b)[1]))
#define EX2_F16X2(out, in) \
    asm("ex2.approx.f16x2 %0, %1;" : "=r"(out) : "r"(in))

__device__ __forceinline__ void cpa16(uint32_t dst, const void* src) {
    asm volatile("cp.async.ca.shared.global [%0], [%1], 16;" :: "r"(dst), "l"(src));
}
#define CP_COMMIT() asm volatile("cp.async.commit_group;" ::: "memory")
#define CP_WAIT0()  asm volatile("cp.async.wait_group 0;" ::: "memory")

__device__ __forceinline__ uint32_t pack_hf2(float a, float b) {
    __half2 h = __floats2half2_rn(a, b);
    return *(uint32_t*)&h;
}

// ======================= scratch =======================
__device__ __half g_q  [BATCH*CLOW *NPIX];   // [b][c][n], scale*log2e folded
__device__ __half g_k  [BATCH*CLOW *NPIX];
__device__ __half g_v  [BATCH*CLOW *NPIX];
__device__ __half g_ao [BATCH*CLOW *NPIX];
__device__ float  g_x  [BATCH*CLOW *NPIX];
__device__ __half g_mid[BATCH*FFN  *NPIX];
__device__ float g_part[3][BATCH][64][2];
__device__ float g_mu[3][BATCH];
__device__ float g_rs[3][BATCH];
__device__ __half g_whq[CLOW*CHIGH];
__device__ __half g_whk[CLOW*CLOW];
__device__ __half g_whv[CLOW*CLOW];
__device__ __half g_whp[CLOW*CLOW];
__device__ __half g_wh1[FFN*CLOW];
__device__ __half g_wh2[CLOW*FFN];

// ================= weight convert (fp32 -> fp16, scale folded for Wq) =================
__global__ void convert_weights(const float* __restrict__ Wq, const float* __restrict__ Wk,
                                const float* __restrict__ Wv, const float* __restrict__ Wp,
                                const float* __restrict__ W1, const float* __restrict__ W2,
                                float qscale) {
    int which = blockIdx.y;
    const float* src; __half* dst; int n; float a = 1.0f;
    switch (which) {
        case 0: src = Wq; dst = g_whq; n = CLOW*CHIGH; a = qscale; break;
        case 1: src = Wk; dst = g_whk; n = CLOW*CLOW;  break;
        case 2: src = Wv; dst = g_whv; n = CLOW*CLOW;  break;
        case 3: src = Wp; dst = g_whp; n = CLOW*CLOW;  break;
        case 4: src = W1; dst = g_wh1; n = FFN*CLOW;   break;
        default: src = W2; dst = g_wh2; n = CLOW*FFN;  break;
    }
    int i = (blockIdx.x * blockDim.x + threadIdx.x) * 4;
    if (i < n) {
        float4 v = *(const float4*)(src + i);
        uint2 p;
        p.x = pack_hf2(v.x*a, v.y*a);
        p.y = pack_hf2(v.z*a, v.w*a);
        *(uint2*)(dst + i) = p;
    }
}

// ================= GroupNorm stats (deterministic 2-stage) =================
__global__ void stats_partial2(const float* __restrict__ high, const float* __restrict__ low) {
    int b = blockIdx.x, ch = blockIdx.y, z = blockIdx.z;
    int perSample = z ? CLOW*NPIX : CHIGH*NPIX;
    int perChunk  = perSample / 32;
    const float* p = (z ? low : high) + (size_t)b*perSample + (size_t)ch*perChunk;
    float s = 0.f, ss = 0.f;
    for (int i = threadIdx.x*4; i < perChunk; i += blockDim.x*4) {
        float4 v = *(const float4*)(p + i);
        s  += v.x + v.y + v.z + v.w;
        ss += v.x*v.x + v.y*v.y + v.z*v.z + v.w*v.w;
    }
    #pragma unroll
    for (int o = 16; o; o >>= 1) {
        s  += __shfl_xor_sync(0xffffffffu, s,  o);
        ss += __shfl_xor_sync(0xffffffffu, ss, o);
    }
    __shared__ float sh[2][8];
    int w = threadIdx.x >> 5;
    if ((threadIdx.x & 31) == 0) { sh[0][w] = s; sh[1][w] = ss; }
    __syncthreads();
    if (threadIdx.x == 0) {
        float S = 0.f, SS = 0.f;
        #pragma unroll
        for (int i = 0; i < 8; i++) { S += sh[0][i]; SS += sh[1][i]; }
        g_part[z][b][ch][0] = S; g_part[z][b][ch][1] = SS;
    }
}

__global__ void stats_final(int base, float cnt0, float cnt1, int nch) {
    int b = blockIdx.x, idx = base + blockIdx.y, t = threadIdx.x;
    float cnt = blockIdx.y ? cnt1 : cnt0;
    float s = g_part[idx][b][t][0], ss = g_part[idx][b][t][1];
    if (nch > 32) { s += g_part[idx][b][t+32][0]; ss += g_part[idx][b][t+32][1]; }
    #pragma unroll
    for (int o = 16; o; o >>= 1) {
        s  += __shfl_xor_sync(0xffffffffu, s,  o);
        ss += __shfl_xor_sync(0xffffffffu, ss, o);
    }
    if (t == 0) {
        float mu = s / cnt;
        float var = ss / cnt - mu * mu;
        g_mu[idx][b] = mu;
        g_rs[idx][b] = rsqrtf(var + 1e-5f);
    }
}

// ================= dual-warpgroup TC GEMM (R7-proven) =================
// INMODE: 0 = fp32 + groupnorm affine, 2 = fp16 raw (cp.async)
// EP: 1 = f16 out; 2 = fp32 out = res + gamma*acc (+stats); 3 = gelu -> f16
template<int INMODE, int EP, int GTILES, int DOSTATS>
__global__ void __launch_bounds__(256, 2)
gemm2(const float* __restrict__ INf, const __half* __restrict__ INh,
      const __half* __restrict__ WA, const __half* __restrict__ WB, int gbase1,
      int K, int cw,
      const float* __restrict__ nw, const float* __restrict__ nbias, int sidx,
      float* __restrict__ outf, __half* __restrict__ outhA, __half* __restrict__ outhB,
      const float* __restrict__ res, const float* __restrict__ gamma) {
    __shared__ __align__(16) __half sA[2][2][GTILES*64*40];
    __shared__ __align__(16) __half sB[2][32*72];

    const int tid = threadIdx.x, warp = tid >> 5, lane = tid & 31;
    const int g = warp >> 2, wi = warp & 3, wt = tid & 127;
    const int b = blockIdx.z, n0 = blockIdx.x * 64;
    const __half* Wg = g ? WB : WA;
    __half* outh = g ? outhB : outhA;
    const int gbase = g ? gbase1 : 0;

    float mu = 0.f, rs = 0.f;
    if (INMODE == 0) { mu = g_mu[sidx][b]; rs = g_rs[sidx][b]; }

    auto stageA = [&](int k0, int bf) {
        #pragma unroll
        for (int it = 0; it < GTILES*2; it++) {
            int idx = wt + it*128;
            int c = idx >> 2, ch = idx & 3;
            cpa16(smem_u32(&sA[bf][g][c*40 + ch*8]),
                  Wg + (size_t)(gbase + c)*K + k0 + ch*8);
        }
    };
    auto stageB = [&](int k0, int bf) {
        int k = tid >> 3, nseg = tid & 7;
        if constexpr (INMODE == 0) {
            int kk = k0 + k;
            float s0 = nw[kk]*rs, t0 = nbias[kk] - mu*s0;
            const float* p = &INf[((size_t)b*K + kk)*NPIX + n0 + nseg*8];
            float4 ra = *(const float4*)p;
            float4 rb = *(const float4*)(p + 4);
            uint4 o;
            o.x = pack_hf2(ra.x*s0+t0, ra.y*s0+t0);
            o.y = pack_hf2(ra.z*s0+t0, ra.w*s0+t0);
            o.z = pack_hf2(rb.x*s0+t0, rb.y*s0+t0);
            o.w = pack_hf2(rb.z*s0+t0, rb.w*s0+t0);
            *(uint4*)&sB[bf][k*72 + nseg*8] = o;
        } else {
            cpa16(smem_u32(&sB[bf][k*72 + nseg*8]),
                  &INh[((size_t)b*K + k0 + k)*NPIX + n0 + nseg*8]);
        }
    };

    float acc[GTILES][8][4] = {};

    stageA(0, 0); stageB(0, 0); CP_COMMIT();
    const int nch = K >> 5;
    for (int i = 0; i < nch; i++) {
        const int bf = i & 1;
        CP_WAIT0();
        __syncthreads();
        if (i + 1 < nch) { stageA((i+1)*32, bf^1); stageB((i+1)*32, bf^1); CP_COMMIT(); }

        #pragma unroll
        for (int ct = 0; ct < GTILES; ct++) {
            uint32_t qa[2][4];
            #pragma unroll
            for (int kc = 0; kc < 2; kc++) {
                uint32_t addr = smem_u32(&sA[bf][g][(ct*64 + wi*16 + (lane & 15))*40
                                                    + kc*16 + (lane >> 4)*8]);
                LDSM_X4(qa[kc][0], qa[kc][1], qa[kc][2], qa[kc][3], addr);
            }
            #pragma unroll
            for (int nt = 0; nt < 8; nt++) {
                uint32_t b0[2], b1[2];
                uint32_t a0 = smem_u32(&sB[bf][(lane & 15)*72 + nt*8]);
                LDSM_X2_T(b0[0], b0[1], a0);
                LDSM_X2_T(b1[0], b1[1], a0 + 16*72*2);
                MMA16816(acc[ct][nt], qa[0], b0);
                MMA16816(acc[ct][nt], qa[1], b1);
            }
        }
    }

    float s_s = 0.f, s_ss = 0.f;
    #pragma unroll
    for (int ct = 0; ct < GTILES; ct++) {
        #pragma unroll
        for (int nt = 0; nt < 8; nt++) {
            int n = nt*8 + (lane & 3)*2;
            int cA = gbase + ct*64 + wi*16 + (lane >> 2), cB = cA + 8;
            size_t oA = ((size_t)b*cw + cA)*NPIX + n0 + n;
            size_t oB = ((size_t)b*cw + cB)*NPIX + n0 + n;
            if constexpr (EP == 1) {
                *(uint32_t*)&outh[oA] = pack_hf2(acc[ct][nt][0], acc[ct][nt][1]);
                *(uint32_t*)&outh[oB] = pack_hf2(acc[ct][nt][2], acc[ct][nt][3]);
            } else if constexpr (EP == 2) {
                float gm = gamma[0];
                float2 rA = *(const float2*)&res[oA];
                float2 rB = *(const float2*)&res[oB];
                float v0 = rA.x + gm*acc[ct][nt][0], v1 = rA.y + gm*acc[ct][nt][1];
                float v2 = rB.x + gm*acc[ct][nt][2], v3 = rB.y + gm*acc[ct][nt][3];
                *(float2*)&outf[oA] = make_float2(v0, v1);
                *(float2*)&outf[oB] = make_float2(v2, v3);
                if (DOSTATS) {
                    s_s  += (v0 + v1) + (v2 + v3);
                    s_ss += v0*v0 + v1*v1 + v2*v2 + v3*v3;
                }
            } else {
                float v0 = acc[ct][nt][0], v1 = acc[ct][nt][1];
                float v2 = acc[ct][nt][2], v3 = acc[ct][nt][3];
                v0 = 0.5f*v0*(1.0f + erff(v0*0.70710678118654752f));
                v1 = 0.5f*v1*(1.0f + erff(v1*0.70710678118654752f));
                v2 = 0.5f*v2*(1.0f + erff(v2*0.70710678118654752f));
                v3 = 0.5f*v3*(1.0f + erff(v3*0.70710678118654752f));
                *(uint32_t*)&outh[oA] = pack_hf2(v0, v1);
                *(uint32_t*)&outh[oB] = pack_hf2(v2, v3);
            }
        }
    }
    if constexpr (DOSTATS) {
        #pragma unroll
        for (int o = 16; o; o >>= 1) {
            s_s  += __shfl_xor_sync(0xffffffffu, s_s,  o);
            s_ss += __shfl_xor_sync(0xffffffffu, s_ss, o);
        }
        __shared__ float shr[2][8];
        if (lane == 0) { shr[0][warp] = s_s; shr[1][warp] = s_ss; }
        __syncthreads();
        if (tid == 0) {
            float S = 0.f, SS = 0.f;
            #pragma unroll
            for (int i = 0; i < 8; i++) { S += shr[0][i]; SS += shr[1][i]; }
            g_part[2][b][blockIdx.x][0] = S; g_part[2][b][blockIdx.x][1] = SS;
        }
    }
}

// ================= flash attention (ALL-fp16 mma accum, exp2-domain, V-ones l-sum) =================
#define QSTR 136
#define KVSTR 72

__device__ __forceinline__ void prefetch_kv(__half* sk, __half* sv,
        const __half* Kb, const __half* Vb, int n0, int tid) {
    #pragma unroll
    for (int i = 0; i < 2; i++) {
        int ch = tid + i * 128;
        int row = ch >> 3, col = ch & 7;
        cpa16(smem_u32(&sk[row*KVSTR + col*8]), Kb + (size_t)row*NPIX + n0 + col*8);
    }
    #pragma unroll
    for (int i = 0; i < 2; i++) {
        int ch = tid + i * 128;
        int row = ch >> 3, col = ch & 7;
        cpa16(smem_u32(&sv[row*KVSTR + col*8]), Vb + (size_t)row*NPIX + n0 + col*8);
    }
}

__global__ void __launch_bounds__(128, 3)
flash_mma(const __half* __restrict__ Qg, const __half* __restrict__ Kg,
          const __half* __restrict__ Vg, __half* __restrict__ Og) {
    __shared__ __align__(16) __half sQ[32*QSTR];
    __shared__ __align__(16) __half sK[2][32*KVSTR];
    __shared__ __align__(16) __half sV[2][40*KVSTR];
    __shared__ __align__(16) float sT[32*132];

    const int tid = threadIdx.x, warp = tid >> 5, lane = tid & 31;
    const int bh = blockIdx.y, m0 = blockIdx.x * 128;
    const __half* Qb = Qg + (size_t)bh * HDIM * NPIX + m0;
    const __half* Kb = Kg + (size_t)bh * HDIM * NPIX;
    const __half* Vb = Vg + (size_t)bh * HDIM * NPIX;

    // ones rows: 2 buffers x 8 rows x 8 chunks = 128 threads exactly
    {
        int bfi = tid >> 6, row = 32 + ((tid >> 3) & 7), chk = tid & 7;
        float v = (row == 32) ? 1.0f : 0.0f;
        uint32_t hv = pack_hf2(v, v);
        uint4 q4 = make_uint4(hv, hv, hv, hv);
        *(uint4*)&sV[bfi][row*KVSTR + chk*8] = q4;
    }

    #pragma unroll
    for (int i = 0; i < 4; i++) {
        int ch = tid + i * 128;
        int row = ch >> 4, col = ch & 15;
        *(uint4*)&sQ[row*QSTR + col*8] = *(const uint4*)(Qb + (size_t)row*NPIX + col*8);
    }
    prefetch_kv(sK[0], sV[0], Kb, Vb, 0, tid);
    CP_COMMIT();
    __syncthreads();

    uint32_t qa[2][2][4];
    #pragma unroll
    for (int mb = 0; mb < 2; mb++)
        #pragma unroll
        for (int kc = 0; kc < 2; kc++) {
            uint32_t addr = smem_u32(&sQ[(kc*16 + ((lane >> 4) & 1)*8 + (lane & 7))*QSTR
                                         + warp*32 + mb*16 + ((lane >> 3) & 1)*8]);
            LDSM_X4_T(qa[mb][kc][0], qa[mb][kc][1], qa[mb][kc][2], qa[mb][kc][3], addr);
        }

    uint32_t Oc[2][5][2] = {};

    for (int nb = 0; nb < 64; nb++) {
        const int buf = nb & 1;
        CP_WAIT0();
        __syncthreads();
        if (nb < 63) {
            prefetch_kv(sK[buf^1], sV[buf^1], Kb, Vb, (nb+1)*64, tid);
            CP_COMMIT();
        }

        // ---- S = Q K^T (fp16 accum) fused with in-place EX2 -> P fragments ----
        uint32_t pa[2][4][4];
        #pragma unroll
        for (int nt = 0; nt < 8; nt++) {
            uint32_t bk0[2], bk1[2];
            uint32_t a0 = smem_u32(&sK[buf][(lane & 15)*KVSTR + nt*8]);
            LDSM_X2_T(bk0[0], bk0[1], a0);
            LDSM_X2_T(bk1[0], bk1[1], a0 + 16*KVSTR*2);
            #pragma unroll
            for (int mb = 0; mb < 2; mb++) {
                uint32_t S[2] = {0u, 0u};
                MMA16816H(S, qa[mb][0], bk0);
                MMA16816H(S, qa[mb][1], bk1);
                EX2_F16X2(S[0], S[0]);
                EX2_F16X2(S[1], S[1]);
                pa[mb][nt >> 1][(nt & 1)*2 + 0] = S[0];
                pa[mb][nt >> 1][(nt & 1)*2 + 1] = S[1];
            }
        }

        // ---- O += P V (fp16 accum; dt=4 = ones rows -> l in col 32) ----
        #pragma unroll
        for (int kc = 0; kc < 4; kc++)
            #pragma unroll
            for (int dt = 0; dt < 5; dt++) {
                uint32_t vb[2];
                uint32_t addr = smem_u32(&sV[buf][(dt*8 + (lane & 7))*KVSTR
                                                  + kc*16 + ((lane >> 3) & 1)*8]);
                LDSM_X2(vb[0], vb[1], addr);
                MMA16816H(Oc[0][dt], pa[0][kc], vb);
                MMA16816H(Oc[1][dt], pa[1][kc], vb);
            }
    }

    // l = col 32 (half0 of Oc[mb][4][0] rows r, Oc[mb][4][1] rows r+8), lanes (lane&3)==0
    float inv[2][2];
    #pragma unroll
    for (int mb = 0; mb < 2; mb++) {
        __half2 h0 = *(__half2*)&Oc[mb][4][0];
        __half2 h1 = *(__half2*)&Oc[mb][4][1];
        float l0 = __shfl_sync(0xffffffffu, __half2float(h0.x), lane & 28);
        float l1 = __shfl_sync(0xffffffffu, __half2float(h1.x), lane & 28);
        inv[mb][0] = 1.0f / l0;
        inv[mb][1] = 1.0f / l1;
    }

    // epilogue: unpack fp16 O, scale, transpose through sT, write ao fp16 [b][c][n]
    #pragma unroll
    for (int mb = 0; mb < 2; mb++) {
        int r = warp*32 + mb*16 + (lane >> 2);
        #pragma unroll
        for (int dt = 0; dt < 4; dt++) {
            int d = dt*8 + (lane & 3)*2;
            __half2 p0 = *(__half2*)&Oc[mb][dt][0];
            __half2 p1 = *(__half2*)&Oc[mb][dt][1];
            sT[(d+0)*132 + r    ] = __half2float(p0.x)*inv[mb][0];
            sT[(d+1)*132 + r    ] = __half2float(p0.y)*inv[mb][0];
            sT[(d+0)*132 + r + 8] = __half2float(p1.x)*inv[mb][1];
            sT[(d+1)*132 + r + 8] = __half2float(p1.y)*inv[mb][1];
        }
    }
    __syncthreads();
    __half* aob = Og + (size_t)bh * HDIM * NPIX + m0;
    #pragma unroll
    for (int i = 0; i < 8; i++) {
        int idx = tid + i*128;
        int d = idx >> 5, seg = idx & 31;
        const float* src = &sT[d*132 + seg*4];
        uint2 p;
        p.x = pack_hf2(src[0], src[1]);
        p.y = pack_hf2(src[2], src[3]);
        *(uint2*)(aob + (size_t)d*NPIX + seg*4) = p;
    }
}

// ================= launch =================
extern "C" void kernel_launch(void* const* d_in, const int* in_sizes, int n_in,
                              void* d_out, int out_size) {
    const float* high  = (const float*)d_in[0];
    const float* low   = (const float*)d_in[1];
    const float* nhw   = (const float*)d_in[2];
    const float* nhb   = (const float*)d_in[3];
    const float* nlw   = (const float*)d_in[4];
    const float* nlb   = (const float*)d_in[5];
    const float* nfw   = (const float*)d_in[6];
    const float* nfb   = (const float*)d_in[7];
    const float* Wq    = (const float*)d_in[8];
    const float* Wk    = (const float*)d_in[9];
    const float* Wv    = (const float*)d_in[10];
    const float* Wproj = (const float*)d_in[11];
    const float* Wffn1 = (const float*)d_in[12];
    const float* Wffn2 = (const float*)d_in[13];
    const float* ga    = (const float*)d_in[14];
    const float* gf    = (const float*)d_in[15];
    float* out = (float*)d_out;

    float *x;
    __half *q, *k, *v, *ao, *mid, *whq, *whk, *whv, *whp, *wh1, *wh2;
    cudaGetSymbolAddress((void**)&q,   g_q);
    cudaGetSymbolAddress((void**)&k,   g_k);
    cudaGetSymbolAddress((void**)&v,   g_v);
    cudaGetSymbolAddress((void**)&ao,  g_ao);
    cudaGetSymbolAddress((void**)&x,   g_x);
    cudaGetSymbolAddress((void**)&mid, g_mid);
    cudaGetSymbolAddress((void**)&whq, g_whq);
    cudaGetSymbolAddress((void**)&whk, g_whk);
    cudaGetSymbolAddress((void**)&whv, g_whv);
    cudaGetSymbolAddress((void**)&whp, g_whp);
    cudaGetSymbolAddress((void**)&wh1, g_wh1);
    cudaGetSymbolAddress((void**)&wh2, g_wh2);

    const float scale = 0.17677669529663687f * 1.44269504088896340736f; // 1/sqrt(32)*log2e
    dim3 gg(NPIX/64, 1, BATCH);

    convert_weights<<<dim3(32, 6), 256>>>(Wq, Wk, Wv, Wproj, Wffn1, Wffn2, scale);
    stats_partial2<<<dim3(BATCH, 32, 2), 256>>>(high, low);
    stats_final<<<dim3(BATCH, 2), 32>>>(0, (float)(CHIGH*NPIX), (float)(CLOW*NPIX), 32);

    gemm2<0,1,1,0><<<gg, 256>>>(high, nullptr, whq, whq, 64, CHIGH, CLOW,
                                nhw, nhb, 0, nullptr, q, q, nullptr, nullptr);
    gemm2<0,1,2,0><<<gg, 256>>>(low, nullptr, whk, whv, 0, CLOW, CLOW,
                                nlw, nlb, 1, nullptr, k, v, nullptr, nullptr);

    flash_mma<<<dim3(NPIX/128, BATCH*HEADS), 128>>>(q, k, v, ao);

    gemm2<2,2,1,1><<<gg, 256>>>(nullptr, ao, whp, whp, 64, CLOW, CLOW,
                                nullptr, nullptr, 0, x, nullptr, nullptr, low, ga);
    stats_final<<<dim3(BATCH, 1), 32>>>(2, (float)(CLOW*NPIX), (float)(CLOW*NPIX), 64);

    gemm2<0,3,2,0><<<gg, 256>>>(x, nullptr, wh1, wh1, 128, CLOW, FFN,
                                nfw, nfb, 2, nullptr, mid, mid, nullptr, nullptr);
    gemm2<2,2,1,0><<<gg, 256>>>(nullptr, mid, wh2, wh2, 64, FFN, CLOW,
                                nullptr, nullptr, 0, out, nullptr, nullptr, x, gf);

    (void)in_sizes; (void)n_in; (void)out_size;
}